// round 2
// baseline (speedup 1.0000x reference)
#include <cuda_runtime.h>
#include <math.h>

#define NPOS 512
#define NNEG 512
#define NALL 1024
#define DIM  512
#define EPSV 1e-5f
#define COSEPS 1e-8f

#define TILE 64
#define DK   32
#define SPAD 68   // padded smem row (floats): 16B-aligned float4 rows, no read conflicts

// ---------------- device scratch (no allocations allowed) ----------------
__device__ float g_rnorm[NALL];          // 1/max(||row||, 1e-8); rows 0..511 = pos, 512..1023 = neg
__device__ float g_t1[NPOS];
__device__ float g_t2[NALL];
__device__ float g_deno[NPOS];
__device__ float g_cospp[NPOS * NPOS];
__device__ float g_loss1;
__device__ float g_bce;

__device__ __forceinline__ float warp_sum(float v) {
#pragma unroll
    for (int o = 16; o; o >>= 1) v += __shfl_xor_sync(0xffffffffu, v, o);
    return v;
}

// ---------------- kernel 0: zero accumulators ----------------
__global__ void init_kernel() {
    int i = blockIdx.x * blockDim.x + threadIdx.x;
    if (i < NPOS) g_deno[i] = 0.f;
    if (i == 0) { g_loss1 = 0.f; g_bce = 0.f; }
}

// ---------------- kernel 1: per-row norm, t1, t2 ----------------
__global__ void row_kernel(const float* __restrict__ pos,
                           const float* __restrict__ neg,
                           const float* __restrict__ w) {
    int row = blockIdx.x;                     // 0..1023
    const float* src = (row < NPOS) ? (pos + row * DIM) : (neg + (row - NPOS) * DIM);
    const float* w1 = w;
    const float* w2 = w + DIM;
    int t = threadIdx.x;                      // 128 threads
    float ss = 0.f, d1 = 0.f, d2 = 0.f;
#pragma unroll 4
    for (int d = t; d < DIM; d += 128) {
        float v = src[d];
        ss = fmaf(v, v, ss);
        d1 = fmaf(v, w1[d], d1);
        d2 = fmaf(v, w2[d], d2);
    }
    ss = warp_sum(ss); d1 = warp_sum(d1); d2 = warp_sum(d2);
    __shared__ float red[3][4];
    int wid = t >> 5, lid = t & 31;
    if (lid == 0) { red[0][wid] = ss; red[1][wid] = d1; red[2][wid] = d2; }
    __syncthreads();
    if (t == 0) {
        float S = red[0][0] + red[0][1] + red[0][2] + red[0][3];
        float D1 = red[1][0] + red[1][1] + red[1][2] + red[1][3];
        float D2 = red[2][0] + red[2][1] + red[2][2] + red[2][3];
        float nrm = fmaxf(sqrtf(S), COSEPS);
        g_rnorm[row] = 1.f / nrm;
        g_t2[row] = D2;
        if (row < NPOS) g_t1[row] = D1;
    }
}

// ---------------- kernel 2: fused pair kernel (dot + t3 + epilogues) ----------------
// grid: (NALL/TILE, NPOS/TILE) = (16, 8); block: 256 threads; 4x4 pairs/thread
__global__ void __launch_bounds__(256, 1) pair_kernel(
    const float* __restrict__ pos, const float* __restrict__ neg,
    const float* __restrict__ w, const float* __restrict__ bptr)
{
    __shared__ float sA[DK][SPAD];   // pos tile, transposed: sA[d][r]
    __shared__ float sB[DK][SPAD];   // allv tile, transposed
    __shared__ float sW[DK];
    __shared__ float sRed[8];

    const int n0 = blockIdx.y * TILE;
    const int m0 = blockIdx.x * TILE;
    const int t  = threadIdx.x;
    const int tx = t & 15, ty = t >> 4;

    const float* w3 = w + 2 * DIM;
    const bool pos_half = (m0 < NPOS);
    const float* Bsrc = pos_half ? pos : neg;
    const int mrow0 = pos_half ? m0 : (m0 - NPOS);

    float dotv[4][4], t3v[4][4];
#pragma unroll
    for (int i = 0; i < 4; i++)
#pragma unroll
        for (int j = 0; j < 4; j++) { dotv[i][j] = 0.f; t3v[i][j] = 0.f; }

    const int lc = t & 31;   // d within chunk (coalesced global reads)
    const int lr = t >> 5;   // row group

    for (int d0 = 0; d0 < DIM; d0 += DK) {
        if (t < DK) sW[t] = w3[d0 + t];
#pragma unroll
        for (int rr = 0; rr < TILE; rr += 8) {
            int r = rr + lr;
            sA[lc][r] = pos [(n0 + r)    * DIM + d0 + lc];
            sB[lc][r] = Bsrc[(mrow0 + r) * DIM + d0 + lc];
        }
        __syncthreads();
#pragma unroll 8
        for (int kk = 0; kk < DK; kk++) {
            float4 av = *(const float4*)&sA[kk][ty * 4];
            float4 bv = *(const float4*)&sB[kk][tx * 4];
            float a[4] = {av.x, av.y, av.z, av.w};
            float b[4] = {bv.x, bv.y, bv.z, bv.w};
            float wv = sW[kk];
#pragma unroll
            for (int i = 0; i < 4; i++)
#pragma unroll
                for (int j = 0; j < 4; j++) {
                    dotv[i][j] = fmaf(a[i], b[j], dotv[i][j]);
                    t3v[i][j]  = fmaf(fabsf(a[i] - b[j]), wv, t3v[i][j]);
                }
        }
        __syncthreads();
    }

    // ---- epilogue ----
    float rn_n[4], rn_m[4], t1v[4], t2v[4];
#pragma unroll
    for (int i = 0; i < 4; i++) {
        int gn = n0 + ty * 4 + i;
        rn_n[i] = g_rnorm[gn];
        t1v[i]  = g_t1[gn];
    }
#pragma unroll
    for (int j = 0; j < 4; j++) {
        int gm = m0 + tx * 4 + j;
        rn_m[j] = g_rnorm[gm];
        t2v[j]  = g_t2[gm];
    }
    float bias = bptr[0];

    float bce_local = 0.f;
    float deno_local[4] = {0.f, 0.f, 0.f, 0.f};

#pragma unroll
    for (int i = 0; i < 4; i++) {
#pragma unroll
        for (int j = 0; j < 4; j++) {
            float c = dotv[i][j] * rn_n[i] * rn_m[j];
            float logit = t1v[i] + t2v[j] + t3v[i][j] + bias;
            float x = pos_half ? -logit : logit;          // label=1 -> softplus(-logit)
            bce_local += fmaxf(x, 0.f) + log1pf(expf(-fabsf(x)));
            if (pos_half) {
                g_cospp[(n0 + ty * 4 + i) * NPOS + (m0 + tx * 4 + j)] = c;
            } else {
                deno_local[i] += expf(c);
            }
        }
    }

    if (!pos_half) {
        // reduce across the 16 tx-lanes sharing each n-row (xor stays within 16-lane half)
#pragma unroll
        for (int i = 0; i < 4; i++) {
            float v = deno_local[i];
            v += __shfl_xor_sync(0xffffffffu, v, 1);
            v += __shfl_xor_sync(0xffffffffu, v, 2);
            v += __shfl_xor_sync(0xffffffffu, v, 4);
            v += __shfl_xor_sync(0xffffffffu, v, 8);
            if ((t & 15) == 0) atomicAdd(&g_deno[n0 + ty * 4 + i], v);
        }
    }

    // block-reduce bce then single atomic
    float bs = warp_sum(bce_local);
    if ((t & 31) == 0) sRed[t >> 5] = bs;
    __syncthreads();
    if (t == 0) {
        float s = 0.f;
#pragma unroll
        for (int k = 0; k < 8; k++) s += sRed[k];
        atomicAdd(&g_bce, s);
    }
}

// ---------------- kernel 3: contrastive term ----------------
__global__ void loss1_kernel() {
    int idx = blockIdx.x * blockDim.x + threadIdx.x;
    int stride = gridDim.x * blockDim.x;
    float local = 0.f;
    for (int k = idx; k < NPOS * NPOS; k += stride) {
        int n = k >> 9;
        float c = g_cospp[k];
        // -log(e^c / (deno + e^c + eps)) = log(deno + e^c + eps) - c
        local += logf(g_deno[n] + expf(c) + EPSV) - c;
    }
    local = warp_sum(local);
    __shared__ float sRed[8];
    int t = threadIdx.x;
    if ((t & 31) == 0) sRed[t >> 5] = local;
    __syncthreads();
    if (t == 0) {
        float s = 0.f;
#pragma unroll
        for (int k = 0; k < (int)(blockDim.x >> 5); k++) s += sRed[k];
        atomicAdd(&g_loss1, s);
    }
}

// ---------------- kernel 4: final combine ----------------
__global__ void final_kernel(float* out) {
    out[0] = g_loss1 + g_bce * (1.0f / (float)NALL);
}

// ---------------- launch ----------------
extern "C" void kernel_launch(void* const* d_in, const int* in_sizes, int n_in,
                              void* d_out, int out_size) {
    const float* pos = (const float*)d_in[0];   // [512,512]
    const float* neg = (const float*)d_in[1];   // [512,512]
    const float* w   = (const float*)d_in[2];   // [1,1536]
    const float* b   = (const float*)d_in[3];   // [1]
    float* out = (float*)d_out;

    init_kernel<<<2, 256>>>();
    row_kernel<<<NALL, 128>>>(pos, neg, w);
    dim3 grid(NALL / TILE, NPOS / TILE);        // (16, 8)
    pair_kernel<<<grid, 256>>>(pos, neg, w, b);
    loss1_kernel<<<148, 256>>>();
    final_kernel<<<1, 1>>>(out);
}